// round 2
// baseline (speedup 1.0000x reference)
#include <cuda_runtime.h>
#include <math.h>

// Problem constants
#define BATCH   4
#define NNODES  325
#define BN      (BATCH * NNODES)   // 1300
#define IDIM    64
#define HDIM    128
#define G4H     (4 * HDIM)         // 512
#define MAXNB   96
#define LN_EPS  1e-5f

// ---------------- scratch (__device__ globals; no allocation) ----------------
__device__ float g_h_lstm[BN * HDIM];
__device__ float g_support[BN * HDIM];
__device__ float g_hgraph[BN * HDIM];
__device__ float g_s[BN * HDIM];
__device__ float g_t[BN * HDIM];
__device__ float g_hatt[BN * HDIM];
__device__ int   g_nbr[BN * MAXNB];
__device__ float g_nbrw[BN * MAXNB];
__device__ int   g_cnt[BN];

__device__ __forceinline__ float sigm(float x) { return 1.0f / (1.0f + expf(-x)); }

// ============================================================================
// K1: fused LSTM cell.  gates = x @ W_ih^T + h @ W_hh^T + b ; activations.
// 8 nodes per block, 512 threads (one per gate-row g in [0,512)).
// ============================================================================
#define NPB 8
__global__ void __launch_bounds__(512)
lstm_kernel(const float* __restrict__ x, const float* __restrict__ h,
            const float* __restrict__ c, const float* __restrict__ W_ih,
            const float* __restrict__ W_hh, const float* __restrict__ b_ih,
            const float* __restrict__ b_hh, float* __restrict__ c_out)
{
    __shared__ __align__(16) float sx[NPB][IDIM];
    __shared__ __align__(16) float sh[NPB][HDIM];
    __shared__ float gbuf[NPB][G4H];

    const int node0 = blockIdx.x * NPB;
    const int tid = threadIdx.x;

    for (int idx = tid; idx < NPB * IDIM; idx += 512) {
        int m = idx >> 6, k = idx & 63;
        int node = node0 + m;
        sx[m][k] = (node < BN) ? x[node * IDIM + k] : 0.0f;
    }
    for (int idx = tid; idx < NPB * HDIM; idx += 512) {
        int m = idx >> 7, k = idx & 127;
        int node = node0 + m;
        sh[m][k] = (node < BN) ? h[node * HDIM + k] : 0.0f;
    }
    __syncthreads();

    const int g = tid;  // gate row 0..511
    float acc[NPB];
#pragma unroll
    for (int m = 0; m < NPB; m++) acc[m] = 0.0f;

    const float4* wx = (const float4*)(W_ih + g * IDIM);
#pragma unroll
    for (int k4 = 0; k4 < IDIM / 4; k4++) {
        float4 w = __ldg(wx + k4);
#pragma unroll
        for (int m = 0; m < NPB; m++) {
            float4 a = *((const float4*)&sx[m][k4 * 4]);
            acc[m] += a.x * w.x + a.y * w.y + a.z * w.z + a.w * w.w;
        }
    }
    const float4* wh = (const float4*)(W_hh + g * HDIM);
#pragma unroll
    for (int k4 = 0; k4 < HDIM / 4; k4++) {
        float4 w = __ldg(wh + k4);
#pragma unroll
        for (int m = 0; m < NPB; m++) {
            float4 a = *((const float4*)&sh[m][k4 * 4]);
            acc[m] += a.x * w.x + a.y * w.y + a.z * w.z + a.w * w.w;
        }
    }
    const float bb = __ldg(b_ih + g) + __ldg(b_hh + g);
#pragma unroll
    for (int m = 0; m < NPB; m++) gbuf[m][g] = acc[m] + bb;
    __syncthreads();

    for (int idx = tid; idx < NPB * HDIM; idx += 512) {
        int m = idx >> 7, u = idx & 127;
        int node = node0 + m;
        if (node < BN) {
            float ig = sigm(gbuf[m][u]);
            float fg = sigm(gbuf[m][HDIM + u]);
            float gg = tanhf(gbuf[m][2 * HDIM + u]);
            float og = sigm(gbuf[m][3 * HDIM + u]);
            float cc = fg * c[node * HDIM + u] + ig * gg;
            float hh = og * tanhf(cc);
            g_h_lstm[node * HDIM + u] = hh;
            c_out[node * HDIM + u] = cc;
        }
    }
}

// ============================================================================
// K2: support = h_lstm @ gc_w   (W is (128,128) row-major, NOT transposed)
// 8 nodes/block, 128 threads (one per output column o).
// ============================================================================
__global__ void __launch_bounds__(128)
gemm_nt_kernel(const float* __restrict__ A, const float* __restrict__ W,
               float* __restrict__ C)
{
    __shared__ __align__(16) float sA[8][HDIM];
    const int m0 = blockIdx.x * 8;
    const int o = threadIdx.x;

    for (int idx = o; idx < 8 * HDIM; idx += 128) {
        int m = idx >> 7, k = idx & 127;
        int node = m0 + m;
        sA[m][k] = (node < BN) ? A[node * HDIM + k] : 0.0f;
    }
    __syncthreads();

    float acc[8];
#pragma unroll
    for (int m = 0; m < 8; m++) acc[m] = 0.0f;

#pragma unroll 4
    for (int k4 = 0; k4 < HDIM / 4; k4++) {
        int k = k4 * 4;
        float w0 = __ldg(W + (k + 0) * HDIM + o);
        float w1 = __ldg(W + (k + 1) * HDIM + o);
        float w2 = __ldg(W + (k + 2) * HDIM + o);
        float w3 = __ldg(W + (k + 3) * HDIM + o);
#pragma unroll
        for (int m = 0; m < 8; m++) {
            float4 a = *((const float4*)&sA[m][k]);
            acc[m] += a.x * w0 + a.y * w1 + a.z * w2 + a.w * w3;
        }
    }
#pragma unroll
    for (int m = 0; m < 8; m++) {
        int node = m0 + m;
        if (node < BN) C[node * HDIM + o] = acc[m];
    }
}

// ============================================================================
// K3: sparse graph conv + CSR build.
// One block per (b,i) row.  h_graph[i] = sum_j adj[i,j]*support[j] + gc_b.
// ============================================================================
__global__ void __launch_bounds__(128)
graphconv_kernel(const float* __restrict__ adj, const float* __restrict__ gc_b)
{
    const int row = blockIdx.x;          // 0..BN-1
    const int b = row / NNODES;
    const int i = row % NNODES;
    __shared__ int   cnt;
    __shared__ int   lst[MAXNB];
    __shared__ float wv[MAXNB];

    if (threadIdx.x == 0) cnt = 0;
    __syncthreads();

    const float* arow = adj + (size_t)b * NNODES * NNODES + (size_t)i * NNODES;
    for (int j = threadIdx.x; j < NNODES; j += 128) {
        float a = arow[j];
        if (a != 0.0f) {
            int p = atomicAdd(&cnt, 1);
            if (p < MAXNB) { lst[p] = j; wv[p] = a; }
        }
    }
    __syncthreads();
    const int cn = min(cnt, MAXNB);
    if (threadIdx.x == 0) g_cnt[row] = cn;
    for (int t = threadIdx.x; t < cn; t += 128) {
        g_nbr[row * MAXNB + t] = lst[t];
        g_nbrw[row * MAXNB + t] = wv[t];
    }

    const int u = threadIdx.x;
    float acc = __ldg(gc_b + u);
    for (int t = 0; t < cn; t++) {
        int j = lst[t];
        acc += wv[t] * g_support[(b * NNODES + j) * HDIM + u];
    }
    g_hgraph[row * HDIM + u] = acc;
}

// ============================================================================
// K4: transposed-weight GEMM:  C = A @ W^T + bias   (W is (128,128) row-major)
// Each thread reads its own W row contiguously (float4); L2-hot.
// ============================================================================
__global__ void __launch_bounds__(128)
gemm_tt_kernel(const float* __restrict__ A, const float* __restrict__ W,
               const float* __restrict__ bias, float* __restrict__ C)
{
    __shared__ __align__(16) float sA[8][HDIM];
    const int m0 = blockIdx.x * 8;
    const int o = threadIdx.x;

    for (int idx = o; idx < 8 * HDIM; idx += 128) {
        int m = idx >> 7, k = idx & 127;
        int node = m0 + m;
        sA[m][k] = (node < BN) ? A[node * HDIM + k] : 0.0f;
    }
    __syncthreads();

    float bs = __ldg(bias + o);
    float acc[8];
#pragma unroll
    for (int m = 0; m < 8; m++) acc[m] = bs;

    const float4* wrow = (const float4*)(W + o * HDIM);
#pragma unroll 4
    for (int k4 = 0; k4 < HDIM / 4; k4++) {
        float4 w = __ldg(wrow + k4);
#pragma unroll
        for (int m = 0; m < 8; m++) {
            float4 a = *((const float4*)&sA[m][k4 * 4]);
            acc[m] += a.x * w.x + a.y * w.y + a.z * w.z + a.w * w.w;
        }
    }
#pragma unroll
    for (int m = 0; m < 8; m++) {
        int node = m0 + m;
        if (node < BN) C[node * HDIM + o] = acc[m];
    }
}

// ============================================================================
// K5: fused sparse attention + softmax + context + LayerNorm.
// One block per (b,i) row, 128 threads = 4 warps.
// scores computed ONLY on nonzero adj entries (exact: exp(-1e9-max) == 0.f).
// ============================================================================
__global__ void __launch_bounds__(128)
attn_kernel(const float* __restrict__ v, const float* __restrict__ ln_g,
            const float* __restrict__ ln_b)
{
    const int row = blockIdx.x;
    const int b = row / NNODES;
    const int tid = threadIdx.x;
    const int lane = tid & 31;
    const int wrp = tid >> 5;

    __shared__ float s_sh[HDIM];
    __shared__ float v_sh[HDIM];
    __shared__ float sc[MAXNB];
    __shared__ int   lst[MAXNB];
    __shared__ float red1[4], red2[4];

    s_sh[tid] = g_s[row * HDIM + tid];
    v_sh[tid] = __ldg(v + tid);
    const int cnt = g_cnt[row];
    for (int t = tid; t < cnt; t += 128) lst[t] = g_nbr[row * MAXNB + t];
    __syncthreads();

    // scores over neighbors (warp t-strided)
    for (int t = wrp; t < cnt; t += 4) {
        const float* tj = g_t + (size_t)(b * NNODES + lst[t]) * HDIM;
        float p = 0.0f;
#pragma unroll
        for (int q = 0; q < 4; q++) {
            int u = lane + q * 32;
            p += tanhf(s_sh[u] + tj[u]) * v_sh[u];
        }
#pragma unroll
        for (int off = 16; off > 0; off >>= 1)
            p += __shfl_xor_sync(0xffffffffu, p, off);
        if (lane == 0) sc[t] = p;
    }
    __syncthreads();

    // softmax over the cnt real entries (warp 0)
    if (wrp == 0) {
        float mx = -1e30f;
        for (int t = lane; t < cnt; t += 32) mx = fmaxf(mx, sc[t]);
#pragma unroll
        for (int off = 16; off > 0; off >>= 1)
            mx = fmaxf(mx, __shfl_xor_sync(0xffffffffu, mx, off));
        float sm = 0.0f;
        for (int t = lane; t < cnt; t += 32) {
            float e = expf(sc[t] - mx);
            sc[t] = e;
            sm += e;
        }
#pragma unroll
        for (int off = 16; off > 0; off >>= 1)
            sm += __shfl_xor_sync(0xffffffffu, sm, off);
        float inv = 1.0f / sm;
        for (int t = lane; t < cnt; t += 32) sc[t] *= inv;
    }
    __syncthreads();

    // context
    const int u = tid;
    float acc = 0.0f;
    for (int t = 0; t < cnt; t++)
        acc += sc[t] * g_hgraph[(size_t)(b * NNODES + lst[t]) * HDIM + u];

    // LayerNorm over H=128 (block reduce)
    float s1 = acc, s2 = acc * acc;
#pragma unroll
    for (int off = 16; off > 0; off >>= 1) {
        s1 += __shfl_xor_sync(0xffffffffu, s1, off);
        s2 += __shfl_xor_sync(0xffffffffu, s2, off);
    }
    if (lane == 0) { red1[wrp] = s1; red2[wrp] = s2; }
    __syncthreads();
    float tot1 = red1[0] + red1[1] + red1[2] + red1[3];
    float tot2 = red2[0] + red2[1] + red2[2] + red2[3];
    float mu = tot1 * (1.0f / HDIM);
    float var = tot2 * (1.0f / HDIM) - mu * mu;
    float out = __ldg(ln_g + u) * (acc - mu) * rsqrtf(var + LN_EPS) + __ldg(ln_b + u);
    g_hatt[row * HDIM + u] = out;
}

// ============================================================================
// K6: combine:  h_new = [h_lstm | h_att] @ comb_w^T + comb_b
// comb_w is (128, 256) row-major.
// ============================================================================
__global__ void __launch_bounds__(128)
comb_kernel(const float* __restrict__ comb_w, const float* __restrict__ comb_b,
            float* __restrict__ out)
{
    __shared__ __align__(16) float sA1[8][HDIM];
    __shared__ __align__(16) float sA2[8][HDIM];
    const int m0 = blockIdx.x * 8;
    const int o = threadIdx.x;

    for (int idx = o; idx < 8 * HDIM; idx += 128) {
        int m = idx >> 7, k = idx & 127;
        int node = m0 + m;
        sA1[m][k] = (node < BN) ? g_h_lstm[node * HDIM + k] : 0.0f;
        sA2[m][k] = (node < BN) ? g_hatt[node * HDIM + k] : 0.0f;
    }
    __syncthreads();

    float bs = __ldg(comb_b + o);
    float acc[8];
#pragma unroll
    for (int m = 0; m < 8; m++) acc[m] = bs;

    const float4* wrow = (const float4*)(comb_w + o * 2 * HDIM);
#pragma unroll 4
    for (int k4 = 0; k4 < HDIM / 4; k4++) {
        float4 w = __ldg(wrow + k4);
#pragma unroll
        for (int m = 0; m < 8; m++) {
            float4 a = *((const float4*)&sA1[m][k4 * 4]);
            acc[m] += a.x * w.x + a.y * w.y + a.z * w.z + a.w * w.w;
        }
    }
#pragma unroll 4
    for (int k4 = 0; k4 < HDIM / 4; k4++) {
        float4 w = __ldg(wrow + HDIM / 4 + k4);
#pragma unroll
        for (int m = 0; m < 8; m++) {
            float4 a = *((const float4*)&sA2[m][k4 * 4]);
            acc[m] += a.x * w.x + a.y * w.y + a.z * w.z + a.w * w.w;
        }
    }
#pragma unroll
    for (int m = 0; m < 8; m++) {
        int node = m0 + m;
        if (node < BN) out[node * HDIM + o] = acc[m];
    }
}

// ============================================================================
extern "C" void kernel_launch(void* const* d_in, const int* in_sizes, int n_in,
                              void* d_out, int out_size)
{
    const float* x      = (const float*)d_in[0];
    const float* adj    = (const float*)d_in[1];
    const float* h      = (const float*)d_in[2];
    const float* c      = (const float*)d_in[3];
    const float* W_ih   = (const float*)d_in[4];
    const float* W_hh   = (const float*)d_in[5];
    const float* b_ih   = (const float*)d_in[6];
    const float* b_hh   = (const float*)d_in[7];
    const float* gc_w   = (const float*)d_in[8];
    const float* gc_b   = (const float*)d_in[9];
    const float* Ws_w   = (const float*)d_in[10];
    const float* Ws_b   = (const float*)d_in[11];
    const float* Wt_w   = (const float*)d_in[12];
    const float* Wt_b   = (const float*)d_in[13];
    const float* v      = (const float*)d_in[14];
    const float* ln_g   = (const float*)d_in[15];
    const float* ln_b   = (const float*)d_in[16];
    const float* comb_w = (const float*)d_in[17];
    const float* comb_b = (const float*)d_in[18];

    float* out = (float*)d_out;              // [0, BN*H) = h_new, [BN*H, 2*BN*H) = c_lstm
    float* c_out = out + (size_t)BN * HDIM;

    const int GB = (BN + 7) / 8;             // 163 tile-blocks

    // scratch pointers come from __device__ globals inside the kernels

    lstm_kernel<<<GB, 512>>>(x, h, c, W_ih, W_hh, b_ih, b_hh, c_out);

    // support = h_lstm @ gc_w
    {
        // A = g_h_lstm (device global); pass via symbol-free path: kernel reads it? No —
        // gemm kernels take explicit pointers; fetch device addresses at first call.
        // We use cudaGetSymbolAddress-free approach: static local pointers resolved once.
        static float* p_hl = nullptr; static float* p_sup = nullptr;
        static float* p_hg = nullptr; static float* p_s = nullptr; static float* p_t = nullptr;
        if (!p_hl) {
            cudaGetSymbolAddress((void**)&p_hl,  g_h_lstm);
            cudaGetSymbolAddress((void**)&p_sup, g_support);
            cudaGetSymbolAddress((void**)&p_hg,  g_hgraph);
            cudaGetSymbolAddress((void**)&p_s,   g_s);
            cudaGetSymbolAddress((void**)&p_t,   g_t);
        }
        gemm_nt_kernel<<<GB, 128>>>(p_hl, gc_w, p_sup);
        graphconv_kernel<<<BN, 128>>>(adj, gc_b);
        gemm_tt_kernel<<<GB, 128>>>(p_hg, Ws_w, Ws_b, p_s);
        gemm_tt_kernel<<<GB, 128>>>(p_hg, Wt_w, Wt_b, p_t);
        attn_kernel<<<BN, 128>>>(v, ln_g, ln_b);
        comb_kernel<<<GB, 128>>>(comb_w, comb_b, out);
    }
}